// round 1
// baseline (speedup 1.0000x reference)
#include <cuda_runtime.h>
#include <math.h>

// ---------------- problem constants ----------------
#define BB   16      // batch (trees)
#define TT   32      // nodes per tree
#define LL   64      // token positions
#define DM   768     // d_model
#define HH   12      // heads
#define HD   64      // head dim
#define FF   2048    // ffn dim
#define ZZ   100     // d_z
#define NMAX 496     // max packed responses = 16*31

enum { OP_NONE = 0, OP_RELU = 1, OP_TANH = 2 };

// ---------------- device scratch (static, no allocation) ----------------
__device__ float g_X  [NMAX * LL * DM];          // activations
__device__ float g_QKV[NMAX * LL * 3 * DM];
__device__ float g_ATT[NMAX * LL * DM];
__device__ float g_Y  [NMAX * LL * DM];
__device__ float g_HID[NMAX * LL * FF];
__device__ float g_Z  [NMAX * LL * ZZ];
__device__ float g_S  [768 * NMAX * NMAX];       // [l*12+h][n][m] attention scores
__device__ float g_MSK[NMAX * LL];               // gathered attention_mask rows
__device__ float g_meanE[NMAX * DM];             // mean over L of gathered emb
__device__ float g_s  [NMAX];                    // anomaly scores
__device__ int   g_Ntot;
__device__ int   g_nresp[BB];
__device__ int   g_next [BB];
__device__ int   g_bidx [NMAX];
__device__ int   g_tidx [NMAX];
__device__ int   g_nodefull[BB * TT];
__device__ int   g_oh      [BB * TT];

// ---------------- setup: ragged packing metadata (device-side!) ----------------
__global__ void setup_kernel(const int* __restrict__ tree_lens) {
    if (threadIdx.x == 0 && blockIdx.x == 0) {
        int tot = 0;
        for (int b = 0; b < BB; b++) {
            int tl = tree_lens[b];
            int nr = tl - 1;
            g_nresp[b] = nr;
            int ne = (int)floor((double)nr * 0.05);
            if (ne < 1) ne = 1;
            g_next[b] = ne;
            for (int j = 1; j < tl; j++) {
                g_bidx[tot] = b;
                g_tidx[tot] = j;
                tot++;
            }
        }
        g_Ntot = tot;
    }
}

// ---------------- gather reply rows + mask ----------------
__global__ void gather_kernel(const float* __restrict__ emb,
                              const float* __restrict__ amask) {
    int n = blockIdx.x;
    int l = blockIdx.y;
    if (n >= g_Ntot) return;
    int bi = g_bidx[n], ti = g_tidx[n];
    const float* src = emb + (((size_t)bi * TT + ti) * LL + l) * DM;
    float* dst = g_X + ((size_t)n * LL + l) * DM;
    for (int d = threadIdx.x; d < DM; d += blockDim.x) dst[d] = src[d];
    if (threadIdx.x == 0)
        g_MSK[n * LL + l] = amask[((size_t)bi * TT + ti) * LL + l];
}

// mean over L of gathered emb (needed at the end)
__global__ void meanE_kernel() {
    int n = blockIdx.x;
    if (n >= g_Ntot) return;
    int d = blockIdx.y * 256 + threadIdx.x;
    float s = 0.f;
    for (int l = 0; l < LL; l++) s += g_X[((size_t)n * LL + l) * DM + d];
    g_meanE[n * DM + d] = s * (1.f / (float)LL);
}

// ---------------- generic NT GEMM: C[M,N] = A[M,K] * W[N,K]^T + bias ----------------
// BM=128, BN=64, BK=16, 256 threads, 8x4 per-thread microtile. M = g_Ntot*64 (dynamic).
template <int OP>
__global__ void __launch_bounds__(256)
gemm_nt(const float* __restrict__ A, const float* __restrict__ W,
        const float* __restrict__ bias, float* __restrict__ C,
        int N, int K) {
    const int BM = 128, BN = 64, BK = 16;
    int M = g_Ntot * LL;
    int m0 = blockIdx.y * BM;
    if (m0 >= M) return;
    int n0 = blockIdx.x * BN;

    __shared__ __align__(16) float As[BK][BM];
    __shared__ __align__(16) float Bs[BK][BN];

    int tid = threadIdx.x;
    int tx = tid & 15;          // 0..15 -> n
    int ty = tid >> 4;          // 0..15 -> m
    int lr = tid >> 2;          // 0..63
    int lc = (tid & 3) * 4;     // 0,4,8,12

    float acc[8][4];
#pragma unroll
    for (int i = 0; i < 8; i++)
#pragma unroll
        for (int j = 0; j < 4; j++) acc[i][j] = 0.f;

    for (int k0 = 0; k0 < K; k0 += BK) {
        // load A tile (transposed into smem)
#pragma unroll
        for (int p = 0; p < 2; p++) {
            int m = m0 + lr + p * 64;
            const float* arow = A + (size_t)m * K + k0 + lc;
            bool mok = (m < M);
#pragma unroll
            for (int j = 0; j < 4; j++) {
                int k = k0 + lc + j;
                As[lc + j][lr + p * 64] = (mok && k < K) ? arow[j] : 0.f;
            }
        }
        // load W tile
        {
            int n = n0 + lr;
            const float* wrow = W + (size_t)n * K + k0 + lc;
            bool nok = (n < N);
#pragma unroll
            for (int j = 0; j < 4; j++) {
                int k = k0 + lc + j;
                Bs[lc + j][lr] = (nok && k < K) ? wrow[j] : 0.f;
            }
        }
        __syncthreads();
#pragma unroll
        for (int kk = 0; kk < BK; kk++) {
            float4 a0 = *reinterpret_cast<const float4*>(&As[kk][ty * 8]);
            float4 a1 = *reinterpret_cast<const float4*>(&As[kk][ty * 8 + 4]);
            float4 bv = *reinterpret_cast<const float4*>(&Bs[kk][tx * 4]);
            float a[8] = {a0.x, a0.y, a0.z, a0.w, a1.x, a1.y, a1.z, a1.w};
            float b[4] = {bv.x, bv.y, bv.z, bv.w};
#pragma unroll
            for (int i = 0; i < 8; i++)
#pragma unroll
                for (int j = 0; j < 4; j++) acc[i][j] = fmaf(a[i], b[j], acc[i][j]);
        }
        __syncthreads();
    }
#pragma unroll
    for (int i = 0; i < 8; i++) {
        int m = m0 + ty * 8 + i;
        if (m >= M) continue;
#pragma unroll
        for (int j = 0; j < 4; j++) {
            int n = n0 + tx * 4 + j;
            if (n >= N) continue;
            float v = acc[i][j] + bias[n];
            if (OP == OP_RELU) v = fmaxf(v, 0.f);
            if (OP == OP_TANH) v = tanhf(v);
            C[(size_t)m * N + n] = v;
        }
    }
}

// ---------------- attention scores: S[lh,n,m] = 0.125*q.k + mask[m,l] ----------------
__global__ void __launch_bounds__(256) scores_kernel() {
    int Nt = g_Ntot;
    int n0 = blockIdx.x * 64;
    int m0 = blockIdx.y * 64;
    if (n0 >= Nt || m0 >= Nt) return;
    int lh = blockIdx.z;
    int l = lh / HH, h = lh % HH;

    __shared__ float Qs[64][65];
    __shared__ float Ks[64][65];

    int tid = threadIdx.x;
    int r = tid >> 2;            // 0..63
    int c0 = (tid & 3) * 16;     // 0,16,32,48
    {
        int n = n0 + r;
        const float* srcq = g_QKV + ((size_t)n * LL + l) * (3 * DM) + h * HD;
        int m = m0 + r;
        const float* srck = g_QKV + ((size_t)m * LL + l) * (3 * DM) + DM + h * HD;
#pragma unroll
        for (int j = 0; j < 16; j++) Qs[r][c0 + j] = (n < Nt) ? srcq[c0 + j] : 0.f;
#pragma unroll
        for (int j = 0; j < 16; j++) Ks[r][c0 + j] = (m < Nt) ? srck[c0 + j] : 0.f;
    }
    __syncthreads();

    int tx = tid & 15, ty = tid >> 4;
    float acc[4][4];
#pragma unroll
    for (int i = 0; i < 4; i++)
#pragma unroll
        for (int j = 0; j < 4; j++) acc[i][j] = 0.f;

#pragma unroll 8
    for (int k = 0; k < 64; k++) {
        float a[4], b[4];
#pragma unroll
        for (int i = 0; i < 4; i++) a[i] = Qs[ty * 4 + i][k];
#pragma unroll
        for (int j = 0; j < 4; j++) b[j] = Ks[tx * 4 + j][k];
#pragma unroll
        for (int i = 0; i < 4; i++)
#pragma unroll
            for (int j = 0; j < 4; j++) acc[i][j] = fmaf(a[i], b[j], acc[i][j]);
    }
#pragma unroll
    for (int i = 0; i < 4; i++) {
        int n = n0 + ty * 4 + i;
        if (n >= Nt) continue;
        float* srow = g_S + ((size_t)lh * NMAX + n) * NMAX;
#pragma unroll
        for (int j = 0; j < 4; j++) {
            int m = m0 + tx * 4 + j;
            if (m >= Nt) continue;
            srow[m] = acc[i][j] * 0.125f + g_MSK[m * LL + l];
        }
    }
}

// ---------------- row softmax over m ----------------
__global__ void softmax_kernel() {
    int n = blockIdx.x;
    int lh = blockIdx.y;
    int Nt = g_Ntot;
    if (n >= Nt) return;
    float* row = g_S + ((size_t)lh * NMAX + n) * NMAX;
    int t = threadIdx.x;  // 128
    __shared__ float red[128];

    float mx = -INFINITY;
    for (int j = t; j < Nt; j += 128) mx = fmaxf(mx, row[j]);
    red[t] = mx; __syncthreads();
    for (int s = 64; s > 0; s >>= 1) { if (t < s) red[t] = fmaxf(red[t], red[t + s]); __syncthreads(); }
    mx = red[0]; __syncthreads();

    float sum = 0.f;
    for (int j = t; j < Nt; j += 128) { float e = __expf(row[j] - mx); row[j] = e; sum += e; }
    red[t] = sum; __syncthreads();
    for (int s = 64; s > 0; s >>= 1) { if (t < s) red[t] += red[t + s]; __syncthreads(); }
    float inv = 1.f / red[0];
    for (int j = t; j < Nt; j += 128) row[j] *= inv;
}

// ---------------- O = P @ V ----------------
__global__ void __launch_bounds__(256) pv_kernel() {
    int Nt = g_Ntot;
    int n0 = blockIdx.x * 64;
    if (n0 >= Nt) return;
    int lh = blockIdx.y;
    int l = lh / HH, h = lh % HH;

    __shared__ float Ps[64][65];
    __shared__ float Vs[64][65];

    int tid = threadIdx.x;
    int r = tid >> 2;
    int c0 = (tid & 3) * 16;
    int tx = tid & 15, ty = tid >> 4;

    float acc[4][4];
#pragma unroll
    for (int i = 0; i < 4; i++)
#pragma unroll
        for (int j = 0; j < 4; j++) acc[i][j] = 0.f;

    for (int m0 = 0; m0 < Nt; m0 += 64) {
        {
            int n = n0 + r;
            const float* prow = g_S + ((size_t)lh * NMAX + n) * NMAX;
#pragma unroll
            for (int j = 0; j < 16; j++) {
                int m = m0 + c0 + j;
                Ps[r][c0 + j] = (n < Nt && m < Nt) ? prow[m] : 0.f;
            }
            int mr = m0 + r;
            const float* vsrc = g_QKV + ((size_t)mr * LL + l) * (3 * DM) + 2 * DM + h * HD;
#pragma unroll
            for (int j = 0; j < 16; j++) Vs[r][c0 + j] = (mr < Nt) ? vsrc[c0 + j] : 0.f;
        }
        __syncthreads();
#pragma unroll 8
        for (int k = 0; k < 64; k++) {
            float a[4], b[4];
#pragma unroll
            for (int i = 0; i < 4; i++) a[i] = Ps[ty * 4 + i][k];
#pragma unroll
            for (int j = 0; j < 4; j++) b[j] = Vs[k][tx * 4 + j];
#pragma unroll
            for (int i = 0; i < 4; i++)
#pragma unroll
                for (int j = 0; j < 4; j++) acc[i][j] = fmaf(a[i], b[j], acc[i][j]);
        }
        __syncthreads();
    }
#pragma unroll
    for (int i = 0; i < 4; i++) {
        int n = n0 + ty * 4 + i;
        if (n >= Nt) continue;
#pragma unroll
        for (int j = 0; j < 4; j++) {
            int d = tx * 4 + j;
            g_ATT[((size_t)n * LL + l) * DM + h * HD + d] = acc[i][j];
        }
    }
}

// ---------------- residual + LayerNorm (in place on X) ----------------
__global__ void add_ln_kernel(float* __restrict__ X, const float* __restrict__ Yv,
                              const float* __restrict__ g, const float* __restrict__ b) {
    int row = blockIdx.x;
    if (row >= g_Ntot * LL) return;
    float* x = X + (size_t)row * DM;
    const float* y = Yv + (size_t)row * DM;
    int t = threadIdx.x;  // 256
    float v[3], s = 0.f, s2 = 0.f;
#pragma unroll
    for (int i = 0; i < 3; i++) {
        float u = x[t + 256 * i] + y[t + 256 * i];
        v[i] = u; s += u; s2 += u * u;
    }
    __shared__ float rs[256], rs2[256];
    rs[t] = s; rs2[t] = s2; __syncthreads();
    for (int st = 128; st > 0; st >>= 1) {
        if (t < st) { rs[t] += rs[t + st]; rs2[t] += rs2[t + st]; }
        __syncthreads();
    }
    float mean = rs[0] * (1.f / (float)DM);
    float var = rs2[0] * (1.f / (float)DM) - mean * mean;
    float inv = rsqrtf(var + 1e-5f);
#pragma unroll
    for (int i = 0; i < 3; i++) {
        int d = t + 256 * i;
        x[d] = (v[i] - mean) * inv * g[d] + b[d];
    }
}

// ---------------- anomaly score per response ----------------
__global__ void anomaly_kernel() {
    int n = blockIdx.x;
    if (n >= g_Ntot) return;
    int t = threadIdx.x;  // 256
    float acc = 0.f;
#pragma unroll
    for (int i = 0; i < 3; i++) {
        int d = t + 256 * i;
        float m = 0.f;
        for (int l = 0; l < LL; l++) m += g_X[((size_t)n * LL + l) * DM + d];
        m *= (1.f / (float)LL);
        float diff = m - g_meanE[n * DM + d];
        acc += diff * diff;
    }
    __shared__ float red[256];
    red[t] = acc; __syncthreads();
    for (int s = 128; s > 0; s >>= 1) { if (t < s) red[t] += red[t + s]; __syncthreads(); }
    if (t == 0) g_s[n] = red[0];
}

// ---------------- per-tree stable top-k selection ----------------
__global__ void select_kernel() {
    int b = threadIdx.x;
    if (b >= BB) return;
    int nr = g_nresp[b];
    int ne = g_next[b];
    bool used[TT];
    int ohf[TT];
#pragma unroll
    for (int j = 0; j < TT; j++) { used[j] = false; ohf[j] = 0; }
    ohf[0] = 1;
    g_nodefull[b * TT + 0] = 0;
    for (int i = 0; i < TT - 1; i++) {
        int node = 0;
        if (i < ne) {
            float best = INFINITY; int bj = 0;
            for (int j = 0; j < nr; j++) {
                if (!used[j] && g_s[j] < best) { best = g_s[j]; bj = j; }
            }
            used[bj] = true;
            node = bj + 1;
            ohf[node] = 1;
        }
        g_nodefull[b * TT + i + 1] = node;
    }
    for (int t = 0; t < TT; t++) g_oh[b * TT + t] = ohf[t];
}

// ---------------- output writers ----------------
__global__ void out_small_kernel(float* __restrict__ out, long long off_oh,
                                 long long off_sc, long long off_tl, int has_sc) {
    int t = blockIdx.x * blockDim.x + threadIdx.x;
    if (t < BB * TT) out[off_oh + t] = (float)g_oh[t];
    else if (t < BB * TT + BB) out[off_tl + (t - BB * TT)] = (float)(1 + g_next[t - BB * TT]);
    else if (t == BB * TT + BB && has_sc) out[off_sc] = 0.f;
}

__global__ void ext_mask_kernel(float* __restrict__ out, long long off) {
    int bt = blockIdx.x;
    out[off + (size_t)bt * LL + threadIdx.x] = (float)g_oh[bt];
}

__global__ void new_msk_kernel(const float* __restrict__ amask,
                               float* __restrict__ out, long long off) {
    int bt = blockIdx.x;
    int b = bt >> 5, t = bt & 31;
    int node = g_nodefull[bt];
    float valid = (t == 0 || (t - 1) < g_next[b]) ? 1.f : 0.f;
    out[off + (size_t)bt * LL + threadIdx.x] =
        amask[((size_t)b * TT + node) * LL + threadIdx.x] * valid;
}

__global__ void new_emb_kernel(const float* __restrict__ emb,
                               float* __restrict__ out, long long off) {
    // 49152 floats per (b,t) slot; 192 blocks of 256 threads per slot
    int bt = blockIdx.x / 192;
    int r = (blockIdx.x % 192) * 256 + threadIdx.x;
    int b = bt >> 5;
    int node = g_nodefull[bt];
    out[off + (size_t)bt * (LL * DM) + r] =
        emb[((size_t)b * TT + node) * (LL * DM) + r];
}

// ---------------- host orchestration ----------------
static void run_layer(float* X, float* QKV, float* ATT, float* Y, float* HID,
                      const float* qkvw, const float* qkvb,
                      const float* outw, const float* outb,
                      const float* g1, const float* b1,
                      const float* w1, const float* c1,
                      const float* w2, const float* c2,
                      const float* g2, const float* b2) {
    const int GY = (NMAX * LL + 127) / 128;  // 248
    gemm_nt<OP_NONE><<<dim3(36, GY), 256>>>(X, qkvw, qkvb, QKV, 3 * DM, DM);
    scores_kernel<<<dim3(8, 8, LL * HH), 256>>>();
    softmax_kernel<<<dim3(NMAX, LL * HH), 128>>>();
    pv_kernel<<<dim3(8, LL * HH), 256>>>();
    gemm_nt<OP_NONE><<<dim3(12, GY), 256>>>(ATT, outw, outb, Y, DM, DM);
    add_ln_kernel<<<NMAX * LL, 256>>>(X, Y, g1, b1);
    gemm_nt<OP_RELU><<<dim3(32, GY), 256>>>(X, w1, c1, HID, FF, DM);
    gemm_nt<OP_NONE><<<dim3(12, GY), 256>>>(HID, w2, c2, Y, DM, FF);
    add_ln_kernel<<<NMAX * LL, 256>>>(X, Y, g2, b2);
}

extern "C" void kernel_launch(void* const* d_in, const int* in_sizes, int n_in,
                              void* d_out, int out_size) {
    const int*   tree_lens = (const int*)d_in[0];
    const float* emb       = (const float*)d_in[1];
    const float* amask     = (const float*)d_in[2];
    const float* P[28];
    for (int i = 3; i < 31; i++) P[i - 3] = (const float*)d_in[i];
    float* out = (float*)d_out;

    // scratch addresses
    float *pX, *pQKV, *pATT, *pY, *pHID, *pZ;
    cudaGetSymbolAddress((void**)&pX, g_X);
    cudaGetSymbolAddress((void**)&pQKV, g_QKV);
    cudaGetSymbolAddress((void**)&pATT, g_ATT);
    cudaGetSymbolAddress((void**)&pY, g_Y);
    cudaGetSymbolAddress((void**)&pHID, g_HID);
    cudaGetSymbolAddress((void**)&pZ, g_Z);

    // output layout (handle presence/absence of the python-int scalar slot)
    const long long NE_ELEMS = (long long)BB * TT * LL * DM;           // 25165824
    const long long TOT_W = 512 + 32768 + 1 + 16 + NE_ELEMS + 32768;   // 25231889
    int has_sc = ((long long)out_size == TOT_W - 1) ? 0 : 1;
    long long off_oh = 0;
    long long off_em = 512;
    long long off_sc = 512 + 32768;
    long long off_tl = off_sc + (has_sc ? 1 : 0);
    long long off_ne = off_tl + 16;
    long long off_nm = off_ne + NE_ELEMS;

    setup_kernel<<<1, 32>>>(tree_lens);
    gather_kernel<<<dim3(NMAX, LL), 256>>>(emb, amask);
    meanE_kernel<<<dim3(NMAX, 3), 256>>>();

    // encoder (2 layers): params 0..11
    for (int i = 0; i < 2; i++) {
        run_layer(pX, pQKV, pATT, pY, pHID,
                  P[0] + (size_t)i * 3 * DM * DM, P[1] + (size_t)i * 3 * DM,
                  P[2] + (size_t)i * DM * DM,     P[3] + (size_t)i * DM,
                  P[4] + (size_t)i * DM,          P[5] + (size_t)i * DM,
                  P[6] + (size_t)i * FF * DM,     P[7] + (size_t)i * FF,
                  P[8] + (size_t)i * DM * FF,     P[9] + (size_t)i * DM,
                  P[10] + (size_t)i * DM,         P[11] + (size_t)i * DM);
    }

    // projections: z = tanh(h @ pe_w^T + pe_b); zd = tanh(z @ pd_w^T + pd_b)
    const int GY = (NMAX * LL + 127) / 128;
    gemm_nt<OP_TANH><<<dim3(2, GY), 256>>>(pX, P[24], P[25], pZ, ZZ, DM);
    gemm_nt<OP_TANH><<<dim3(12, GY), 256>>>(pZ, P[26], P[27], pX, DM, ZZ);

    // decoder (2 layers): params 12..23
    for (int i = 0; i < 2; i++) {
        run_layer(pX, pQKV, pATT, pY, pHID,
                  P[12] + (size_t)i * 3 * DM * DM, P[13] + (size_t)i * 3 * DM,
                  P[14] + (size_t)i * DM * DM,     P[15] + (size_t)i * DM,
                  P[16] + (size_t)i * DM,          P[17] + (size_t)i * DM,
                  P[18] + (size_t)i * FF * DM,     P[19] + (size_t)i * FF,
                  P[20] + (size_t)i * DM * FF,     P[21] + (size_t)i * DM,
                  P[22] + (size_t)i * DM,          P[23] + (size_t)i * DM);
    }

    anomaly_kernel<<<NMAX, 256>>>();
    select_kernel<<<1, 32>>>();

    out_small_kernel<<<3, 256>>>(out, off_oh, off_sc, off_tl, has_sc);
    ext_mask_kernel<<<BB * TT, LL>>>(out, off_em);
    new_msk_kernel<<<BB * TT, LL>>>(amask, out, off_nm);
    new_emb_kernel<<<BB * TT * 192, 256>>>(emb, out, off_ne);
}